// round 8
// baseline (speedup 1.0000x reference)
#include <cuda_runtime.h>
#include <math.h>

// Problem constants (fixed by the reference)
#define NN 20000
#define EE 160000

// ---------------- scratch (device globals; no runtime allocation) ----------
__device__ __align__(256) float g_buf0[NN * 1024]; // pre-agg transformed feats
__device__ __align__(256) float g_buf1[NN * 512];  // h1 / h3
__device__ int   g_cnt[NN];           // degree counts, then fill cursors
__device__ int   g_off[NN + 1];       // CSR offsets (by dst)
__device__ float g_dinv[NN];          // deg^-0.5 (deg includes self loop)
__device__ int   g_srcs[EE];          // CSR: src node per edge slot
__device__ float g_w[EE];             // CSR: dinv[src] per edge slot
__device__ int   g_is64;              // 1 if edge_index is int64, 0 if int32

// ---------------- dtype detection ----------------
// jnp.int64 is silently demoted to int32 when jax x64 is disabled. Detect at
// runtime: true int64 values (< 20000) have all-zero high words; int32 data
// interpreted the same way has random node-ids there.
__global__ void k_detect(const unsigned int* __restrict__ ei) {
    if (threadIdx.x == 0 && blockIdx.x == 0) {
        int is64 = 1;
        for (int i = 0; i < 256; i++) {
            if (ei[2 * i + 1] != 0u) { is64 = 0; break; }
        }
        g_is64 = is64;
    }
}

__device__ __forceinline__ int edge_at(const void* ei, long long idx) {
    if (g_is64) return (int)((const long long*)ei)[idx];
    return ((const int*)ei)[idx];
}

// ---------------- graph preprocessing ----------------
__global__ void k_zero(int n) {
    int i = blockIdx.x * blockDim.x + threadIdx.x;
    if (i < n) g_cnt[i] = 0;
}

__global__ void k_count(const void* __restrict__ ei, int e) {
    int i = blockIdx.x * blockDim.x + threadIdx.x;
    if (i < e) {
        int d = edge_at(ei, (long long)e + i);   // dst row of edge_index
        if ((unsigned)d < (unsigned)NN) atomicAdd(&g_cnt[d], 1);
    }
}

// single-block scan over 20000 counts: offsets + dinv + cursor reset
__global__ void k_scan(int n) {
    __shared__ int sums[512];
    const int CH = 40;                    // 512*40 = 20480 >= 20000
    int t = threadIdx.x;
    int base = t * CH;

    int local = 0;
    for (int i = 0; i < CH; i++) {
        int idx = base + i;
        if (idx < n) local += g_cnt[idx];
    }
    sums[t] = local;
    __syncthreads();
    for (int off = 1; off < 512; off <<= 1) {
        int v = (t >= off) ? sums[t - off] : 0;
        __syncthreads();
        sums[t] += v;
        __syncthreads();
    }
    int run = sums[t] - local;            // exclusive prefix for this chunk
    for (int i = 0; i < CH; i++) {
        int idx = base + i;
        if (idx < n) {
            int c = g_cnt[idx];
            g_off[idx] = run;
            run += c;
            g_dinv[idx] = rsqrtf((float)(c + 1));  // +1 self loop, deg>=1
            g_cnt[idx] = 0;                        // reuse as fill cursor
        }
    }
    if (t == 511) g_off[n] = sums[511];
}

__global__ void k_fill(const void* __restrict__ ei, int e) {
    int i = blockIdx.x * blockDim.x + threadIdx.x;
    if (i < e) {
        int s = edge_at(ei, i);
        int d = edge_at(ei, (long long)e + i);
        if ((unsigned)s >= (unsigned)NN || (unsigned)d >= (unsigned)NN) return;
        int pos = g_off[d] + atomicAdd(&g_cnt[d], 1);
        g_srcs[pos] = s;
        g_w[pos] = g_dinv[s];
    }
}

// ---------------- symmetric-normalized aggregation (CSR gather) ------------
// out[i] = (sum_{e: dst=i} h[src_e]*dinv[src_e] + h[i]*dinv[i]) * dinv[i] + b
template<int D>
__global__ __launch_bounds__(256) void k_agg(const float* __restrict__ h,
                                             const float* __restrict__ bias,
                                             float* __restrict__ out, int n) {
    constexpr int TPN = D / 4;            // threads per node (float4 lanes)
    constexpr int NPB = 256 / TPN;        // nodes per block
    int node = blockIdx.x * NPB + threadIdx.x / TPN;
    if (node >= n) return;
    int lane = threadIdx.x % TPN;

    const float4* hv = (const float4*)h;
    float di = g_dinv[node];

    float4 acc = hv[(size_t)node * TPN + lane];   // self-loop contribution
    acc.x *= di; acc.y *= di; acc.z *= di; acc.w *= di;

    int p = g_off[node], end = g_off[node + 1];
    for (; p + 1 < end; p += 2) {         // 2-way unroll for MLP
        int s0 = g_srcs[p], s1 = g_srcs[p + 1];
        float w0 = g_w[p],  w1 = g_w[p + 1];
        float4 v0 = hv[(size_t)s0 * TPN + lane];
        float4 v1 = hv[(size_t)s1 * TPN + lane];
        acc.x += v0.x * w0 + v1.x * w1;
        acc.y += v0.y * w0 + v1.y * w1;
        acc.z += v0.z * w0 + v1.z * w1;
        acc.w += v0.w * w0 + v1.w * w1;
    }
    if (p < end) {
        int s = g_srcs[p]; float w = g_w[p];
        float4 v = hv[(size_t)s * TPN + lane];
        acc.x += v.x * w; acc.y += v.y * w; acc.z += v.z * w; acc.w += v.w * w;
    }

    float4 b = ((const float4*)bias)[lane];
    float4 o;
    o.x = acc.x * di + b.x;
    o.y = acc.y * di + b.y;
    o.z = acc.z * di + b.z;
    o.w = acc.w * di + b.w;
    ((float4*)out)[(size_t)node * TPN + lane] = o;
}

// ---------------- fp32 SGEMM: C[n,m] = sum_k A[n,k] * Bop[k,m] -------------
// BT=true : B is [M,K] row-major (use B^T, i.e. X @ W.T)
// BT=false: B is [K,M] row-major (plain X @ W)
template<bool BT>
__global__ __launch_bounds__(256) void k_gemm(const float* __restrict__ A,
                                              const float* __restrict__ B,
                                              float* __restrict__ C,
                                              int nrows, int K, int M) {
    const int BM = 128, BN = 128, BK = 16;
    __shared__ float As[BK][BM];
    __shared__ float Bs[BK][BN];

    int tid = threadIdx.x;
    int tx = tid % 16, ty = tid / 16;
    int rowBase = blockIdx.y * BM;
    int colBase = blockIdx.x * BN;

    float acc[8][8] = {};

    for (int k0 = 0; k0 < K; k0 += BK) {
        // A tile: 128 rows x 16 k, transposed into As[k][m]
        #pragma unroll
        for (int l = 0; l < 2; l++) {
            int q = tid * 2 + l;          // 0..511 float4s
            int r = q >> 2;
            int kk = (q & 3) * 4;
            float4 v = make_float4(0.f, 0.f, 0.f, 0.f);
            int gr = rowBase + r;
            if (gr < nrows)
                v = *(const float4*)(A + (size_t)gr * K + k0 + kk);
            As[kk + 0][r] = v.x; As[kk + 1][r] = v.y;
            As[kk + 2][r] = v.z; As[kk + 3][r] = v.w;
        }
        // B tile
        if constexpr (BT) {               // B[M,K]: same transpose pattern
            #pragma unroll
            for (int l = 0; l < 2; l++) {
                int q = tid * 2 + l;
                int r = q >> 2;
                int kk = (q & 3) * 4;
                float4 v = *(const float4*)(B + (size_t)(colBase + r) * K + k0 + kk);
                Bs[kk + 0][r] = v.x; Bs[kk + 1][r] = v.y;
                Bs[kk + 2][r] = v.z; Bs[kk + 3][r] = v.w;
            }
        } else {                          // B[K,M]: direct contiguous copy
            #pragma unroll
            for (int l = 0; l < 2; l++) {
                int q = tid * 2 + l;
                int kr = q >> 5;          // 32 float4 per k-row
                int c4 = q & 31;
                float4 v = *(const float4*)(B + (size_t)(k0 + kr) * M + colBase + c4 * 4);
                *(float4*)&Bs[kr][c4 * 4] = v;
            }
        }
        __syncthreads();

        #pragma unroll
        for (int k = 0; k < BK; k++) {
            float a[8], b[8];
            *(float4*)&a[0] = *(const float4*)&As[k][ty * 8];
            *(float4*)&a[4] = *(const float4*)&As[k][ty * 8 + 4];
            *(float4*)&b[0] = *(const float4*)&Bs[k][tx * 8];
            *(float4*)&b[4] = *(const float4*)&Bs[k][tx * 8 + 4];
            #pragma unroll
            for (int i = 0; i < 8; i++)
                #pragma unroll
                for (int j = 0; j < 8; j++)
                    acc[i][j] += a[i] * b[j];
        }
        __syncthreads();
    }

    #pragma unroll
    for (int i = 0; i < 8; i++) {
        int gr = rowBase + ty * 8 + i;
        if (gr < nrows) {
            float* cp = C + (size_t)gr * M + colBase + tx * 8;
            *(float4*)cp       = make_float4(acc[i][0], acc[i][1], acc[i][2], acc[i][3]);
            *(float4*)(cp + 4) = make_float4(acc[i][4], acc[i][5], acc[i][6], acc[i][7]);
        }
    }
}

// ---------------- launch ----------------
extern "C" void kernel_launch(void* const* d_in, const int* in_sizes, int n_in,
                              void* d_out, int out_size) {
    const float* X  = (const float*)d_in[0];        // [N,1024]
    const void*  ei = d_in[1];                      // [2,E] int32 or int64
    const float* W1 = (const float*)d_in[2];        // [512,1024]
    const float* b1 = (const float*)d_in[3];        // [512]
    const float* W2 = (const float*)d_in[4];        // [128,512]
    const float* b2 = (const float*)d_in[5];        // [128]
    const float* b3 = (const float*)d_in[6];        // [512]
    const float* b4 = (const float*)d_in[7];        // [1024]
    const float* H1 = (const float*)d_in[8];        // [128,128]
    float* out = (float*)d_out;

    const int n = NN;
    const int e = in_sizes[1] / 2;

    float *buf0, *buf1;
    cudaGetSymbolAddress((void**)&buf0, g_buf0);
    cudaGetSymbolAddress((void**)&buf1, g_buf1);

    // output layout: (z, h2, h4) flattened in return order
    float* z  = out;
    float* h2 = out + (size_t)n * 128;
    float* h4 = out + (size_t)n * 256;

    dim3 blk(256);
    int rtiles = (n + 127) / 128;

    // graph prep
    k_detect<<<1, 32>>>((const unsigned int*)ei);
    k_zero <<<(n + 255) / 256, 256>>>(n);
    k_count<<<(e + 255) / 256, 256>>>(ei, e);
    k_scan <<<1, 512>>>(n);
    k_fill <<<(e + 255) / 256, 256>>>(ei, e);

    // conv1: h = X @ W1^T -> agg -> h1 (buf1)
    k_gemm<true><<<dim3(4, rtiles), blk>>>(X, W1, buf0, n, 1024, 512);
    k_agg<512><<<(n + 1) / 2, 256>>>(buf0, b1, buf1, n);

    // conv2: h = h1 @ W2^T -> agg -> h2 (output)
    k_gemm<true><<<dim3(1, rtiles), blk>>>(buf1, W2, buf0, n, 512, 128);
    k_agg<128><<<(n + 7) / 8, 256>>>(buf0, b2, h2, n);

    // head: z = h2 @ head1 (output)
    k_gemm<false><<<dim3(1, rtiles), blk>>>(h2, H1, z, n, 128, 128);

    // conv3 (tied W2^T): h = z @ W2 -> agg -> h3 (buf1)
    k_gemm<false><<<dim3(4, rtiles), blk>>>(z, W2, buf0, n, 128, 512);
    k_agg<512><<<(n + 1) / 2, 256>>>(buf0, b3, buf1, n);

    // conv4 (tied W1^T): h = h3 @ W1 -> agg -> h4 (output)
    k_gemm<false><<<dim3(8, rtiles), blk>>>(buf1, W1, buf0, n, 512, 1024);
    k_agg<1024><<<n, 256>>>(buf0, b4, h4, n);
}

// round 9
// speedup vs baseline: 1.3314x; 1.3314x over previous
#include <cuda_runtime.h>
#include <math.h>
#include <stdint.h>

// Problem constants (fixed by the reference)
#define NN 20000
#define EE 160000

// ---------------- scratch (device globals; no runtime allocation) ----------
__device__ __align__(256) float g_buf0[NN * 1024]; // pre-agg transformed feats
__device__ __align__(256) float g_buf1[NN * 512];  // h1 / h3
__device__ int   g_cnt[NN];           // degree counts, then fill cursors
__device__ int   g_off[NN + 1];       // CSR offsets (by dst)
__device__ float g_dinv[NN];          // deg^-0.5 (deg includes self loop)
__device__ int   g_srcs[EE];          // CSR: src node per edge slot
__device__ float g_w[EE];             // CSR: dinv[src] per edge slot
__device__ int   g_is64;              // 1 if edge_index is int64, 0 if int32

// ---------------- dtype detection ----------------
// jnp.int64 is silently demoted to int32 when jax x64 is disabled. Detect at
// runtime: true int64 values (< 20000) have all-zero high words; int32 data
// interpreted the same way has random node-ids there.
__global__ void k_detect(const unsigned int* __restrict__ ei) {
    if (threadIdx.x == 0 && blockIdx.x == 0) {
        int is64 = 1;
        for (int i = 0; i < 256; i++) {
            if (ei[2 * i + 1] != 0u) { is64 = 0; break; }
        }
        g_is64 = is64;
    }
}

__device__ __forceinline__ int edge_at(const void* ei, long long idx) {
    if (g_is64) return (int)((const long long*)ei)[idx];
    return ((const int*)ei)[idx];
}

// ---------------- graph preprocessing ----------------
__global__ void k_zero(int n) {
    int i = blockIdx.x * blockDim.x + threadIdx.x;
    if (i < n) g_cnt[i] = 0;
}

__global__ void k_count(const void* __restrict__ ei, int e) {
    int i = blockIdx.x * blockDim.x + threadIdx.x;
    if (i < e) {
        int d = edge_at(ei, (long long)e + i);   // dst row of edge_index
        if ((unsigned)d < (unsigned)NN) atomicAdd(&g_cnt[d], 1);
    }
}

// single-block scan over 20000 counts: offsets + dinv + cursor reset
__global__ void k_scan(int n) {
    __shared__ int sums[512];
    const int CH = 40;                    // 512*40 = 20480 >= 20000
    int t = threadIdx.x;
    int base = t * CH;

    int local = 0;
    for (int i = 0; i < CH; i++) {
        int idx = base + i;
        if (idx < n) local += g_cnt[idx];
    }
    sums[t] = local;
    __syncthreads();
    for (int off = 1; off < 512; off <<= 1) {
        int v = (t >= off) ? sums[t - off] : 0;
        __syncthreads();
        sums[t] += v;
        __syncthreads();
    }
    int run = sums[t] - local;            // exclusive prefix for this chunk
    for (int i = 0; i < CH; i++) {
        int idx = base + i;
        if (idx < n) {
            int c = g_cnt[idx];
            g_off[idx] = run;
            run += c;
            g_dinv[idx] = rsqrtf((float)(c + 1));  // +1 self loop, deg>=1
            g_cnt[idx] = 0;                        // reuse as fill cursor
        }
    }
    if (t == 511) g_off[n] = sums[511];
}

__global__ void k_fill(const void* __restrict__ ei, int e) {
    int i = blockIdx.x * blockDim.x + threadIdx.x;
    if (i < e) {
        int s = edge_at(ei, i);
        int d = edge_at(ei, (long long)e + i);
        if ((unsigned)s >= (unsigned)NN || (unsigned)d >= (unsigned)NN) return;
        int pos = g_off[d] + atomicAdd(&g_cnt[d], 1);
        g_srcs[pos] = s;
        g_w[pos] = g_dinv[s];
    }
}

// ---------------- symmetric-normalized aggregation (CSR gather) ------------
// out[i] = (sum_{e: dst=i} h[src_e]*dinv[src_e] + h[i]*dinv[i]) * dinv[i] + b
template<int D>
__global__ __launch_bounds__(256) void k_agg(const float* __restrict__ h,
                                             const float* __restrict__ bias,
                                             float* __restrict__ out, int n) {
    constexpr int TPN = D / 4;            // threads per node (float4 lanes)
    constexpr int NPB = 256 / TPN;        // nodes per block
    int node = blockIdx.x * NPB + threadIdx.x / TPN;
    if (node >= n) return;
    int lane = threadIdx.x % TPN;

    const float4* hv = (const float4*)h;
    float di = g_dinv[node];

    float4 acc = hv[(size_t)node * TPN + lane];   // self-loop contribution
    acc.x *= di; acc.y *= di; acc.z *= di; acc.w *= di;

    int p = g_off[node], end = g_off[node + 1];
    for (; p + 1 < end; p += 2) {         // 2-way unroll for MLP
        int s0 = g_srcs[p], s1 = g_srcs[p + 1];
        float w0 = g_w[p],  w1 = g_w[p + 1];
        float4 v0 = hv[(size_t)s0 * TPN + lane];
        float4 v1 = hv[(size_t)s1 * TPN + lane];
        acc.x += v0.x * w0 + v1.x * w1;
        acc.y += v0.y * w0 + v1.y * w1;
        acc.z += v0.z * w0 + v1.z * w1;
        acc.w += v0.w * w0 + v1.w * w1;
    }
    if (p < end) {
        int s = g_srcs[p]; float w = g_w[p];
        float4 v = hv[(size_t)s * TPN + lane];
        acc.x += v.x * w; acc.y += v.y * w; acc.z += v.z * w; acc.w += v.w * w;
    }

    float4 b = ((const float4*)bias)[lane];
    float4 o;
    o.x = acc.x * di + b.x;
    o.y = acc.y * di + b.y;
    o.z = acc.z * di + b.z;
    o.w = acc.w * di + b.w;
    ((float4*)out)[(size_t)node * TPN + lane] = o;
}

// ---------------- tf32 tensor-core GEMM (3xTF32 compensated) ---------------
// C[n,m] = sum_k A[n,k] * Bop[k,m], fp32-class accuracy on the tensor pipe.
// BT=true : B is [M,K] row-major (use B^T)
// BT=false: B is [K,M] row-major
//
// Block 128x128, BK=16, 8 warps in 2x4, warp tile 64x32, mma.m16n8k8.
// A and B tiles stay fp32 in smem; hi/lo tf32 split happens in registers.

__device__ __forceinline__ void tf32split(float x, uint32_t& hi, uint32_t& lo) {
    uint32_t h;
    asm("cvt.rna.tf32.f32 %0, %1;" : "=r"(h) : "f"(x));
    float r = x - __uint_as_float(h);
    uint32_t l;
    asm("cvt.rna.tf32.f32 %0, %1;" : "=r"(l) : "f"(r));
    hi = h; lo = l;
}

__device__ __forceinline__ void mma_tf32(float* c, const uint32_t* a,
                                         const uint32_t* b) {
    asm volatile(
        "mma.sync.aligned.m16n8k8.row.col.f32.tf32.tf32.f32 "
        "{%0,%1,%2,%3}, {%4,%5,%6,%7}, {%8,%9}, {%0,%1,%2,%3};\n"
        : "+f"(c[0]), "+f"(c[1]), "+f"(c[2]), "+f"(c[3])
        : "r"(a[0]), "r"(a[1]), "r"(a[2]), "r"(a[3]), "r"(b[0]), "r"(b[1]));
}

template<bool BT>
__device__ __forceinline__ void fetch_tiles(const float* __restrict__ A,
        const float* __restrict__ B, int nrows, int K, int M,
        int rowBase, int colBase, int k0, int tid,
        float4 pa[2], float4 pb[2]) {
    #pragma unroll
    for (int l = 0; l < 2; l++) {
        int q = tid * 2 + l;              // 0..511 float4 slots
        int r = q >> 2;
        int kk = (q & 3) * 4;
        int gr = rowBase + r;
        pa[l] = (gr < nrows) ? *(const float4*)(A + (size_t)gr * K + k0 + kk)
                             : make_float4(0.f, 0.f, 0.f, 0.f);
        if (BT) {
            pb[l] = *(const float4*)(B + (size_t)(colBase + r) * K + k0 + kk);
        } else {
            int kr = q >> 5, c4 = q & 31;
            pb[l] = *(const float4*)(B + (size_t)(k0 + kr) * M + colBase + c4 * 4);
        }
    }
}

template<bool BT>
__device__ __forceinline__ void store_tiles(float As[][136], float Bs[][136],
        int tid, const float4 pa[2], const float4 pb[2]) {
    #pragma unroll
    for (int l = 0; l < 2; l++) {
        int q = tid * 2 + l;
        int r = q >> 2;
        int kk = (q & 3) * 4;
        As[kk + 0][r] = pa[l].x; As[kk + 1][r] = pa[l].y;
        As[kk + 2][r] = pa[l].z; As[kk + 3][r] = pa[l].w;
        if (BT) {
            Bs[kk + 0][r] = pb[l].x; Bs[kk + 1][r] = pb[l].y;
            Bs[kk + 2][r] = pb[l].z; Bs[kk + 3][r] = pb[l].w;
        } else {
            int kr = q >> 5, c4 = q & 31;
            *(float4*)&Bs[kr][c4 * 4] = pb[l];
        }
    }
}

template<bool BT>
__global__ __launch_bounds__(256, 1) void k_gemm_tf32(
        const float* __restrict__ A, const float* __restrict__ B,
        float* __restrict__ C, int nrows, int K, int M) {
    const int BM = 128, BN = 128, BK = 16;
    __shared__ float As[BK][BM + 8];     // stride 136 ≡ 8 mod 32: conflict-free
    __shared__ float Bs[BK][BN + 8];

    int tid = threadIdx.x;
    int rowBase = blockIdx.y * BM;
    int colBase = blockIdx.x * BN;

    int lane = tid & 31, warp = tid >> 5;
    int wm = warp >> 2, wn = warp & 3;    // 2 x 4 warp grid
    int gid = lane >> 2, tig = lane & 3;

    float acc[4][4][4];
    #pragma unroll
    for (int i = 0; i < 4; i++)
        #pragma unroll
        for (int j = 0; j < 4; j++)
            #pragma unroll
            for (int r = 0; r < 4; r++) acc[i][j][r] = 0.f;

    float4 pa[2], pb[2];
    fetch_tiles<BT>(A, B, nrows, K, M, rowBase, colBase, 0, tid, pa, pb);
    store_tiles<BT>(As, Bs, tid, pa, pb);
    __syncthreads();

    for (int k0 = 0; k0 < K; k0 += BK) {
        bool more = (k0 + BK) < K;
        if (more)
            fetch_tiles<BT>(A, B, nrows, K, M, rowBase, colBase, k0 + BK,
                            tid, pa, pb);

        #pragma unroll
        for (int ks = 0; ks < BK; ks += 8) {
            uint32_t ah[4][4], al[4][4], bh[4][2], bl[4][2];
            #pragma unroll
            for (int mt = 0; mt < 4; mt++) {
                int rm = wm * 64 + mt * 16 + gid;
                float a0 = As[ks + tig][rm];
                float a1 = As[ks + tig][rm + 8];
                float a2 = As[ks + tig + 4][rm];
                float a3 = As[ks + tig + 4][rm + 8];
                tf32split(a0, ah[mt][0], al[mt][0]);
                tf32split(a1, ah[mt][1], al[mt][1]);
                tf32split(a2, ah[mt][2], al[mt][2]);
                tf32split(a3, ah[mt][3], al[mt][3]);
            }
            #pragma unroll
            for (int nt = 0; nt < 4; nt++) {
                int cn = wn * 32 + nt * 8 + gid;
                float b0 = Bs[ks + tig][cn];
                float b1 = Bs[ks + tig + 4][cn];
                tf32split(b0, bh[nt][0], bl[nt][0]);
                tf32split(b1, bh[nt][1], bl[nt][1]);
            }
            #pragma unroll
            for (int mt = 0; mt < 4; mt++)
                #pragma unroll
                for (int nt = 0; nt < 4; nt++) {
                    mma_tf32(acc[mt][nt], al[mt], bh[nt]);  // correction terms
                    mma_tf32(acc[mt][nt], ah[mt], bl[nt]);  // first
                    mma_tf32(acc[mt][nt], ah[mt], bh[nt]);
                }
        }
        __syncthreads();
        if (more) {
            store_tiles<BT>(As, Bs, tid, pa, pb);
            __syncthreads();
        }
    }

    // epilogue: c0/c1 at (row, 2*tig), c2/c3 at (row+8, 2*tig)
    #pragma unroll
    for (int mt = 0; mt < 4; mt++) {
        int r0 = rowBase + wm * 64 + mt * 16 + gid;
        #pragma unroll
        for (int nt = 0; nt < 4; nt++) {
            int c = colBase + wn * 32 + nt * 8 + 2 * tig;
            if (r0 < nrows)
                *(float2*)(C + (size_t)r0 * M + c) =
                    make_float2(acc[mt][nt][0], acc[mt][nt][1]);
            if (r0 + 8 < nrows)
                *(float2*)(C + (size_t)(r0 + 8) * M + c) =
                    make_float2(acc[mt][nt][2], acc[mt][nt][3]);
        }
    }
}

// ---------------- launch ----------------
extern "C" void kernel_launch(void* const* d_in, const int* in_sizes, int n_in,
                              void* d_out, int out_size) {
    const float* X  = (const float*)d_in[0];        // [N,1024]
    const void*  ei = d_in[1];                      // [2,E] int32 or int64
    const float* W1 = (const float*)d_in[2];        // [512,1024]
    const float* b1 = (const float*)d_in[3];        // [512]
    const float* W2 = (const float*)d_in[4];        // [128,512]
    const float* b2 = (const float*)d_in[5];        // [128]
    const float* b3 = (const float*)d_in[6];        // [512]
    const float* b4 = (const float*)d_in[7];        // [1024]
    const float* H1 = (const float*)d_in[8];        // [128,128]
    float* out = (float*)d_out;

    const int n = NN;
    const int e = in_sizes[1] / 2;

    float *buf0, *buf1;
    cudaGetSymbolAddress((void**)&buf0, g_buf0);
    cudaGetSymbolAddress((void**)&buf1, g_buf1);

    // output layout: (z, h2, h4) flattened in return order
    float* z  = out;
    float* h2 = out + (size_t)n * 128;
    float* h4 = out + (size_t)n * 256;

    dim3 blk(256);
    int rtiles = (n + 127) / 128;

    // graph prep
    k_detect<<<1, 32>>>((const unsigned int*)ei);
    k_zero <<<(n + 255) / 256, 256>>>(n);
    k_count<<<(e + 255) / 256, 256>>>(ei, e);
    k_scan <<<1, 512>>>(n);
    k_fill <<<(e + 255) / 256, 256>>>(ei, e);

    // conv1: h = X @ W1^T -> agg -> h1 (buf1)
    k_gemm_tf32<true><<<dim3(4, rtiles), blk>>>(X, W1, buf0, n, 1024, 512);
    k_agg<512><<<(n + 1) / 2, 256>>>(buf0, b1, buf1, n);

    // conv2: h = h1 @ W2^T -> agg -> h2 (output)
    k_gemm_tf32<true><<<dim3(1, rtiles), blk>>>(buf1, W2, buf0, n, 512, 128);
    k_agg<128><<<(n + 7) / 8, 256>>>(buf0, b2, h2, n);

    // head: z = h2 @ head1 (output)
    k_gemm_tf32<false><<<dim3(1, rtiles), blk>>>(h2, H1, z, n, 128, 128);

    // conv3 (tied W2^T): h = z @ W2 -> agg -> h3 (buf1)
    k_gemm_tf32<false><<<dim3(4, rtiles), blk>>>(z, W2, buf0, n, 128, 512);
    k_agg<512><<<(n + 1) / 2, 256>>>(buf0, b3, buf1, n);

    // conv4 (tied W1^T): h = h3 @ W1 -> agg -> h4 (output)
    k_gemm_tf32<false><<<dim3(8, rtiles), blk>>>(buf1, W1, buf0, n, 512, 1024);
    k_agg<1024><<<n, 256>>>(buf0, b4, h4, n);
}

// round 10
// speedup vs baseline: 1.3547x; 1.0175x over previous
#include <cuda_runtime.h>
#include <cuda_bf16.h>
#include <math.h>
#include <stdint.h>

// Problem constants (fixed by the reference)
#define NN 20000
#define EE 160000

// ---------------- scratch (device globals; no runtime allocation) ----------
__device__ __align__(256) float g_buf0[NN * 1024]; // scratch A
__device__ __align__(256) float g_buf1[NN * 512];  // scratch B
__device__ int   g_cnt[NN];           // degree counts, then fill cursors
__device__ int   g_off[NN + 1];       // CSR offsets (by dst)
__device__ float g_dinv[NN];          // deg^-0.5 (deg includes self loop)
__device__ int   g_srcs[EE];          // CSR: src node per edge slot
__device__ float g_w[EE];             // CSR: dinv[src] per edge slot
__device__ int   g_is64;              // 1 if edge_index is int64, 0 if int32
__device__ int   g_bsum[128];         // per-block degree partial sums
__device__ float g_zbias[1024];       // all-zero bias (device globals zero-init)

// ---------------- dtype detection ----------------
__global__ void k_detect(const unsigned int* __restrict__ ei) {
    if (threadIdx.x == 0 && blockIdx.x == 0) {
        int is64 = 1;
        for (int i = 0; i < 256; i++) {
            if (ei[2 * i + 1] != 0u) { is64 = 0; break; }
        }
        g_is64 = is64;
    }
}

__device__ __forceinline__ int edge_at(const void* ei, long long idx) {
    if (g_is64) return (int)((const long long*)ei)[idx];
    return ((const int*)ei)[idx];
}

// ---------------- graph preprocessing ----------------
__global__ void k_zero(int n) {
    int i = blockIdx.x * blockDim.x + threadIdx.x;
    if (i < n) g_cnt[i] = 0;
}

__global__ void k_count(const void* __restrict__ ei, int e) {
    int i = blockIdx.x * blockDim.x + threadIdx.x;
    if (i < e) {
        int d = edge_at(ei, (long long)e + i);   // dst row of edge_index
        if ((unsigned)d < (unsigned)NN) atomicAdd(&g_cnt[d], 1);
    }
}

// 3-phase parallel exclusive scan over g_cnt -> g_off, plus dinv + cursor reset
__global__ void k_scan1(int n) {                  // grid = nb, block = 256
    __shared__ int sh[256];
    int i = blockIdx.x * 256 + threadIdx.x;
    sh[threadIdx.x] = (i < n) ? g_cnt[i] : 0;
    __syncthreads();
    for (int o = 128; o > 0; o >>= 1) {
        if (threadIdx.x < o) sh[threadIdx.x] += sh[threadIdx.x + o];
        __syncthreads();
    }
    if (threadIdx.x == 0) g_bsum[blockIdx.x] = sh[0];
}

__global__ void k_scan2(int nb) {                 // 1 block, 128 threads
    __shared__ int sh[128];
    int t = threadIdx.x;
    int v = (t < nb) ? g_bsum[t] : 0;
    sh[t] = v;
    __syncthreads();
    for (int o = 1; o < 128; o <<= 1) {
        int x = (t >= o) ? sh[t - o] : 0;
        __syncthreads();
        sh[t] += x;
        __syncthreads();
    }
    if (t < nb) g_bsum[t] = sh[t] - v;            // exclusive block prefix
    if (t == 127) g_off[NN] = sh[127];            // grand total
}

__global__ void k_scan3(int n) {                  // grid = nb, block = 256
    __shared__ int sh[256];
    int t = threadIdx.x;
    int i = blockIdx.x * 256 + t;
    int c = (i < n) ? g_cnt[i] : 0;
    sh[t] = c;
    __syncthreads();
    for (int o = 1; o < 256; o <<= 1) {
        int x = (t >= o) ? sh[t - o] : 0;
        __syncthreads();
        sh[t] += x;
        __syncthreads();
    }
    if (i < n) {
        g_off[i]  = g_bsum[blockIdx.x] + sh[t] - c;
        g_dinv[i] = rsqrtf((float)(c + 1));       // +1 self loop
        g_cnt[i]  = 0;                            // reuse as fill cursor
    }
}

__global__ void k_fill(const void* __restrict__ ei, int e) {
    int i = blockIdx.x * blockDim.x + threadIdx.x;
    if (i < e) {
        int s = edge_at(ei, i);
        int d = edge_at(ei, (long long)e + i);
        if ((unsigned)s >= (unsigned)NN || (unsigned)d >= (unsigned)NN) return;
        int pos = g_off[d] + atomicAdd(&g_cnt[d], 1);
        g_srcs[pos] = s;
        g_w[pos] = g_dinv[s];
    }
}

// ---------------- symmetric-normalized aggregation (CSR gather) ------------
// out[i] = (sum_{e: dst=i} h[src_e]*dinv[src_e] + h[i]*dinv[i]) * dinv[i] + b
template<int D>
__global__ __launch_bounds__(256) void k_agg(const float* __restrict__ h,
                                             const float* __restrict__ bias,
                                             float* __restrict__ out, int n) {
    constexpr int TPN = D / 4;            // threads per node (float4 lanes)
    constexpr int NPB = 256 / TPN;        // nodes per block
    int node = blockIdx.x * NPB + threadIdx.x / TPN;
    if (node >= n) return;
    int lane = threadIdx.x % TPN;

    const float4* hv = (const float4*)h;
    float di = g_dinv[node];

    float4 acc = hv[(size_t)node * TPN + lane];   // self-loop contribution
    acc.x *= di; acc.y *= di; acc.z *= di; acc.w *= di;

    int p = g_off[node], end = g_off[node + 1];
    for (; p + 1 < end; p += 2) {
        int s0 = g_srcs[p], s1 = g_srcs[p + 1];
        float w0 = g_w[p],  w1 = g_w[p + 1];
        float4 v0 = hv[(size_t)s0 * TPN + lane];
        float4 v1 = hv[(size_t)s1 * TPN + lane];
        acc.x += v0.x * w0 + v1.x * w1;
        acc.y += v0.y * w0 + v1.y * w1;
        acc.z += v0.z * w0 + v1.z * w1;
        acc.w += v0.w * w0 + v1.w * w1;
    }
    if (p < end) {
        int s = g_srcs[p]; float w = g_w[p];
        float4 v = hv[(size_t)s * TPN + lane];
        acc.x += v.x * w; acc.y += v.y * w; acc.z += v.z * w; acc.w += v.w * w;
    }

    float4 b = ((const float4*)bias)[lane];
    float4 o;
    o.x = acc.x * di + b.x;
    o.y = acc.y * di + b.y;
    o.z = acc.z * di + b.z;
    o.w = acc.w * di + b.w;
    ((float4*)out)[(size_t)node * TPN + lane] = o;
}

// ---------------- bf16x3 tensor-core GEMM ----------------------------------
// C[n,m] = sum_k A[n,k]*Bop[k,m] (+ bias[m]), fp32-class accuracy.
// BT=true : B is [M,K] row-major (use B^T)
// BT=false: B is [K,M] row-major
// Each fp32 element is split ONCE per block into bf16 hi/lo smem tiles at
// tile-store time; inner loop is pure LDS + mma.m16n8k16.bf16, 3 mma per pair
// (ah*bh + ah*bl + al*bh). Tiles stored [m][k] / [n][k] so A (and BT-B) copy
// without transpose; row stride 24 bf16 (48B) is conflict-free for the
// fragment load pattern (8 rows x 4 k-pairs per wavefront hit distinct banks).

#define ASTR 24   // bf16 elements per smem tile row (16 data + 8 pad)

__device__ __forceinline__ void bsplit(float x, unsigned short& h,
                                       unsigned short& l) {
    __nv_bfloat16 bh = __float2bfloat16(x);
    float r = x - __bfloat162float(bh);
    __nv_bfloat16 bl = __float2bfloat16(r);
    h = *reinterpret_cast<unsigned short*>(&bh);
    l = *reinterpret_cast<unsigned short*>(&bl);
}

__device__ __forceinline__ void mma_bf16(float* c, const uint32_t* a,
                                         const uint32_t* b) {
    asm volatile(
        "mma.sync.aligned.m16n8k16.row.col.f32.bf16.bf16.f32 "
        "{%0,%1,%2,%3}, {%4,%5,%6,%7}, {%8,%9}, {%0,%1,%2,%3};\n"
        : "+f"(c[0]), "+f"(c[1]), "+f"(c[2]), "+f"(c[3])
        : "r"(a[0]), "r"(a[1]), "r"(a[2]), "r"(a[3]), "r"(b[0]), "r"(b[1]));
}

template<bool BT>
__device__ __forceinline__ void fetch_tiles(const float* __restrict__ A,
        const float* __restrict__ B, int nrows, int K, int M,
        int rowBase, int colBase, int k0, int tid,
        float4 pa[2], float4 pb[2]) {
    #pragma unroll
    for (int l = 0; l < 2; l++) {
        int q = tid * 2 + l;              // 0..511 float4 slots
        int r = q >> 2;
        int kk = (q & 3) * 4;
        int gr = rowBase + r;
        pa[l] = (gr < nrows) ? *(const float4*)(A + (size_t)gr * K + k0 + kk)
                             : make_float4(0.f, 0.f, 0.f, 0.f);
        if (BT) {
            pb[l] = *(const float4*)(B + (size_t)(colBase + r) * K + k0 + kk);
        } else {
            int kr = q >> 5, c4 = q & 31;
            pb[l] = *(const float4*)(B + (size_t)(k0 + kr) * M + colBase + c4 * 4);
        }
    }
}

template<bool BT>
__device__ __forceinline__ void store_tiles(unsigned short* Ah,
        unsigned short* Al, unsigned short* Bh, unsigned short* Bl,
        int tid, const float4 pa[2], const float4 pb[2]) {
    #pragma unroll
    for (int l = 0; l < 2; l++) {
        int q = tid * 2 + l;
        int r = q >> 2;
        int kk = (q & 3) * 4;
        const float* av = (const float*)&pa[l];
        #pragma unroll
        for (int j = 0; j < 4; j++)
            bsplit(av[j], Ah[r * ASTR + kk + j], Al[r * ASTR + kk + j]);
        const float* bv = (const float*)&pb[l];
        if (BT) {
            #pragma unroll
            for (int j = 0; j < 4; j++)
                bsplit(bv[j], Bh[r * ASTR + kk + j], Bl[r * ASTR + kk + j]);
        } else {
            int kr = q >> 5, c4 = q & 31;
            #pragma unroll
            for (int j = 0; j < 4; j++)
                bsplit(bv[j], Bh[(c4 * 4 + j) * ASTR + kr],
                              Bl[(c4 * 4 + j) * ASTR + kr]);
        }
    }
}

template<bool BT>
__global__ __launch_bounds__(256, 1) void k_gemm_bf16x3(
        const float* __restrict__ A, const float* __restrict__ B,
        float* __restrict__ C, const float* __restrict__ bias,
        int nrows, int K, int M) {
    const int BM = 128, BN = 128, BK = 16;
    __shared__ __align__(16) unsigned short Ah[BM * ASTR];
    __shared__ __align__(16) unsigned short Al[BM * ASTR];
    __shared__ __align__(16) unsigned short Bh[BN * ASTR];
    __shared__ __align__(16) unsigned short Bl[BN * ASTR];

    int tid = threadIdx.x;
    int rowBase = blockIdx.y * BM;
    int colBase = blockIdx.x * BN;

    int lane = tid & 31, warp = tid >> 5;
    int wm = warp >> 2, wn = warp & 3;    // 2 x 4 warp grid, warp tile 64x32
    int gid = lane >> 2, tig = lane & 3;

    float acc[4][4][4];
    #pragma unroll
    for (int i = 0; i < 4; i++)
        #pragma unroll
        for (int j = 0; j < 4; j++)
            #pragma unroll
            for (int r = 0; r < 4; r++) acc[i][j][r] = 0.f;

    float4 pa[2], pb[2];
    fetch_tiles<BT>(A, B, nrows, K, M, rowBase, colBase, 0, tid, pa, pb);
    store_tiles<BT>(Ah, Al, Bh, Bl, tid, pa, pb);
    __syncthreads();

    for (int k0 = 0; k0 < K; k0 += BK) {
        bool more = (k0 + BK) < K;
        if (more)
            fetch_tiles<BT>(A, B, nrows, K, M, rowBase, colBase, k0 + BK,
                            tid, pa, pb);

        uint32_t ah[4][4], al[4][4], bh[4][2], bl[4][2];
        #pragma unroll
        for (int mt = 0; mt < 4; mt++) {
            int rm = wm * 64 + mt * 16 + gid;
            ah[mt][0] = *(const uint32_t*)&Ah[rm * ASTR + 2 * tig];
            ah[mt][1] = *(const uint32_t*)&Ah[(rm + 8) * ASTR + 2 * tig];
            ah[mt][2] = *(const uint32_t*)&Ah[rm * ASTR + 2 * tig + 8];
            ah[mt][3] = *(const uint32_t*)&Ah[(rm + 8) * ASTR + 2 * tig + 8];
            al[mt][0] = *(const uint32_t*)&Al[rm * ASTR + 2 * tig];
            al[mt][1] = *(const uint32_t*)&Al[(rm + 8) * ASTR + 2 * tig];
            al[mt][2] = *(const uint32_t*)&Al[rm * ASTR + 2 * tig + 8];
            al[mt][3] = *(const uint32_t*)&Al[(rm + 8) * ASTR + 2 * tig + 8];
        }
        #pragma unroll
        for (int nt = 0; nt < 4; nt++) {
            int cn = wn * 32 + nt * 8 + gid;
            bh[nt][0] = *(const uint32_t*)&Bh[cn * ASTR + 2 * tig];
            bh[nt][1] = *(const uint32_t*)&Bh[cn * ASTR + 2 * tig + 8];
            bl[nt][0] = *(const uint32_t*)&Bl[cn * ASTR + 2 * tig];
            bl[nt][1] = *(const uint32_t*)&Bl[cn * ASTR + 2 * tig + 8];
        }
        #pragma unroll
        for (int mt = 0; mt < 4; mt++)
            #pragma unroll
            for (int nt = 0; nt < 4; nt++) {
                mma_bf16(acc[mt][nt], al[mt], bh[nt]);  // correction terms
                mma_bf16(acc[mt][nt], ah[mt], bl[nt]);
                mma_bf16(acc[mt][nt], ah[mt], bh[nt]);  // main term
            }
        __syncthreads();
        if (more) {
            store_tiles<BT>(Ah, Al, Bh, Bl, tid, pa, pb);
            __syncthreads();
        }
    }

    // epilogue: c0/c1 at (row, 2*tig), c2/c3 at (row+8, 2*tig); optional bias
    #pragma unroll
    for (int mt = 0; mt < 4; mt++) {
        int r0 = rowBase + wm * 64 + mt * 16 + gid;
        #pragma unroll
        for (int nt = 0; nt < 4; nt++) {
            int c = colBase + wn * 32 + nt * 8 + 2 * tig;
            float bx = 0.f, by = 0.f;
            if (bias) { bx = bias[c]; by = bias[c + 1]; }
            if (r0 < nrows)
                *(float2*)(C + (size_t)r0 * M + c) =
                    make_float2(acc[mt][nt][0] + bx, acc[mt][nt][1] + by);
            if (r0 + 8 < nrows)
                *(float2*)(C + (size_t)(r0 + 8) * M + c) =
                    make_float2(acc[mt][nt][2] + bx, acc[mt][nt][3] + by);
        }
    }
}

// ---------------- launch ----------------
extern "C" void kernel_launch(void* const* d_in, const int* in_sizes, int n_in,
                              void* d_out, int out_size) {
    const float* X  = (const float*)d_in[0];        // [N,1024]
    const void*  ei = d_in[1];                      // [2,E] int32 or int64
    const float* W1 = (const float*)d_in[2];        // [512,1024]
    const float* b1 = (const float*)d_in[3];        // [512]
    const float* W2 = (const float*)d_in[4];        // [128,512]
    const float* b2 = (const float*)d_in[5];        // [128]
    const float* b3 = (const float*)d_in[6];        // [512]
    const float* b4 = (const float*)d_in[7];        // [1024]
    const float* H1 = (const float*)d_in[8];        // [128,128]
    float* out = (float*)d_out;

    const int n = NN;
    const int e = in_sizes[1] / 2;

    float *buf0, *buf1, *zb;
    cudaGetSymbolAddress((void**)&buf0, g_buf0);
    cudaGetSymbolAddress((void**)&buf1, g_buf1);
    cudaGetSymbolAddress((void**)&zb,   g_zbias);

    // output layout: (z, h2, h4) flattened in return order
    float* z  = out;
    float* h2 = out + (size_t)n * 128;
    float* h4 = out + (size_t)n * 256;

    dim3 blk(256);
    int rtiles = (n + 127) / 128;
    int nb = (n + 255) / 256;   // scan blocks

    // graph prep
    k_detect<<<1, 32>>>((const unsigned int*)ei);
    k_zero <<<(n + 255) / 256, 256>>>(n);
    k_count<<<(e + 255) / 256, 256>>>(ei, e);
    k_scan1<<<nb, 256>>>(n);
    k_scan2<<<1, 128>>>(nb);
    k_scan3<<<nb, 256>>>(n);
    k_fill <<<(e + 255) / 256, 256>>>(ei, e);

    // conv1: t = X @ W1^T ; h1 = agg(t) + b1          (agg D=512)
    k_gemm_bf16x3<true><<<dim3(4, rtiles), blk>>>(X, W1, buf0, nullptr,
                                                  n, 1024, 512);
    k_agg<512><<<(n + 1) / 2, 256>>>(buf0, b1, buf1, n);

    // conv2: t = h1 @ W2^T ; h2 = agg(t) + b2         (agg D=128)
    k_gemm_bf16x3<true><<<dim3(1, rtiles), blk>>>(buf1, W2, buf0, nullptr,
                                                  n, 512, 128);
    k_agg<128><<<(n + 7) / 8, 256>>>(buf0, b2, h2, n);

    // head: z = h2 @ head1
    k_gemm_bf16x3<false><<<dim3(1, rtiles), blk>>>(h2, H1, z, nullptr,
                                                   n, 128, 128);

    // conv3 (tied W2^T), commuted: h3 = (agg z) @ W2 + b3   (agg D=128)
    k_agg<128><<<(n + 7) / 8, 256>>>(z, zb, buf0, n);
    k_gemm_bf16x3<false><<<dim3(4, rtiles), blk>>>(buf0, W2, buf1, b3,
                                                   n, 128, 512);

    // conv4 (tied W1^T), commuted: h4 = (agg h3) @ W1 + b4  (agg D=512)
    k_agg<512><<<(n + 1) / 2, 256>>>(buf1, zb, buf0, n);
    k_gemm_bf16x3<false><<<dim3(8, rtiles), blk>>>(buf0, W1, h4, b4,
                                                   n, 512, 1024);
}

// round 11
// speedup vs baseline: 2.0307x; 1.4990x over previous
#include <cuda_runtime.h>
#include <cuda_bf16.h>
#include <math.h>
#include <stdint.h>

// Problem constants (fixed by the reference)
#define NN 20000
#define EE 160000

typedef unsigned short u16;

// ---------------- scratch (device globals; no runtime allocation) ----------
__device__ __align__(16) u16   g_xh[NN * 1024];   // X split hi
__device__ __align__(16) u16   g_xl[NN * 1024];   // X split lo
__device__ __align__(16) u16   g_ah[NN * 512];    // activation planes hi
__device__ __align__(16) u16   g_al[NN * 512];    // activation planes lo
__device__ __align__(16) float g_t [NN * 512];    // fp32 GEMM output scratch
// weight planes (native [M,K] layouts for every GEMM)
__device__ __align__(16) u16 g_w1h [512 * 1024], g_w1l [512 * 1024];
__device__ __align__(16) u16 g_w1th[1024 * 512], g_w1tl[1024 * 512];
__device__ __align__(16) u16 g_w2h [128 * 512],  g_w2l [128 * 512];
__device__ __align__(16) u16 g_w2th[512 * 128],  g_w2tl[512 * 128];
__device__ __align__(16) u16 g_h1th[128 * 128],  g_h1tl[128 * 128];

__device__ int   g_cnt[NN];           // degree counts, then fill cursors
__device__ int   g_off[NN + 1];       // CSR offsets (by dst)
__device__ float g_dinv[NN];          // deg^-0.5 (deg includes self loop)
__device__ int   g_srcs[EE];          // CSR: src node per edge slot
__device__ float g_w[EE];             // CSR: dinv[src] per edge slot
__device__ int   g_is64;              // 1 if edge_index is int64, 0 if int32
__device__ int   g_bsum[128];         // per-block degree partial sums
__device__ float g_zbias[1024];       // all-zero bias (zero-initialized)

// ---------------- helpers ----------------
__device__ __forceinline__ void bsplit(float x, u16& h, u16& l) {
    __nv_bfloat16 bh = __float2bfloat16(x);
    float r = x - __bfloat162float(bh);
    __nv_bfloat16 bl = __float2bfloat16(r);
    h = *reinterpret_cast<u16*>(&bh);
    l = *reinterpret_cast<u16*>(&bl);
}

// ---------------- dtype detection ----------------
__global__ void k_detect(const unsigned int* __restrict__ ei) {
    if (threadIdx.x == 0 && blockIdx.x == 0) {
        int is64 = 1;
        for (int i = 0; i < 256; i++) {
            if (ei[2 * i + 1] != 0u) { is64 = 0; break; }
        }
        g_is64 = is64;
    }
}

__device__ __forceinline__ int edge_at(const void* ei, long long idx) {
    if (g_is64) return (int)((const long long*)ei)[idx];
    return ((const int*)ei)[idx];
}

// ---------------- graph preprocessing ----------------
__global__ void k_zero(int n) {
    int i = blockIdx.x * blockDim.x + threadIdx.x;
    if (i < n) g_cnt[i] = 0;
}

__global__ void k_count(const void* __restrict__ ei, int e) {
    int i = blockIdx.x * blockDim.x + threadIdx.x;
    if (i < e) {
        int d = edge_at(ei, (long long)e + i);
        if ((unsigned)d < (unsigned)NN) atomicAdd(&g_cnt[d], 1);
    }
}

__global__ void k_scan1(int n) {                  // grid = nb, block = 256
    __shared__ int sh[256];
    int i = blockIdx.x * 256 + threadIdx.x;
    sh[threadIdx.x] = (i < n) ? g_cnt[i] : 0;
    __syncthreads();
    for (int o = 128; o > 0; o >>= 1) {
        if (threadIdx.x < o) sh[threadIdx.x] += sh[threadIdx.x + o];
        __syncthreads();
    }
    if (threadIdx.x == 0) g_bsum[blockIdx.x] = sh[0];
}

__global__ void k_scan2(int nb) {                 // 1 block, 128 threads
    __shared__ int sh[128];
    int t = threadIdx.x;
    int v = (t < nb) ? g_bsum[t] : 0;
    sh[t] = v;
    __syncthreads();
    for (int o = 1; o < 128; o <<= 1) {
        int x = (t >= o) ? sh[t - o] : 0;
        __syncthreads();
        sh[t] += x;
        __syncthreads();
    }
    if (t < nb) g_bsum[t] = sh[t] - v;
    if (t == 127) g_off[NN] = sh[127];
}

__global__ void k_scan3(int n) {                  // grid = nb, block = 256
    __shared__ int sh[256];
    int t = threadIdx.x;
    int i = blockIdx.x * 256 + t;
    int c = (i < n) ? g_cnt[i] : 0;
    sh[t] = c;
    __syncthreads();
    for (int o = 1; o < 256; o <<= 1) {
        int x = (t >= o) ? sh[t - o] : 0;
        __syncthreads();
        sh[t] += x;
        __syncthreads();
    }
    if (i < n) {
        g_off[i]  = g_bsum[blockIdx.x] + sh[t] - c;
        g_dinv[i] = rsqrtf((float)(c + 1));       // +1 self loop
        g_cnt[i]  = 0;                            // reuse as fill cursor
    }
}

__global__ void k_fill(const void* __restrict__ ei, int e) {
    int i = blockIdx.x * blockDim.x + threadIdx.x;
    if (i < e) {
        int s = edge_at(ei, i);
        int d = edge_at(ei, (long long)e + i);
        if ((unsigned)s >= (unsigned)NN || (unsigned)d >= (unsigned)NN) return;
        int pos = g_off[d] + atomicAdd(&g_cnt[d], 1);
        g_srcs[pos] = s;
        g_w[pos] = g_dinv[s];
    }
}

// ---------------- operand splitting (fp32 -> bf16 hi/lo planes) ------------
__global__ void k_split(const float* __restrict__ in, u16* __restrict__ hi,
                        u16* __restrict__ lo, int count4) {
    int i = blockIdx.x * blockDim.x + threadIdx.x;
    if (i < count4) {
        float4 v = ((const float4*)in)[i];
        ushort4 h4, l4;
        bsplit(v.x, h4.x, l4.x); bsplit(v.y, h4.y, l4.y);
        bsplit(v.z, h4.z, l4.z); bsplit(v.w, h4.w, l4.w);
        ((ushort4*)hi)[i] = h4;
        ((ushort4*)lo)[i] = l4;
    }
}

// transpose split: in [R,C] fp32 row-major -> out [C,R] bf16 planes
__global__ void k_split_t(const float* __restrict__ in, u16* __restrict__ hi,
                          u16* __restrict__ lo, int R, int C) {
    int idx = blockIdx.x * blockDim.x + threadIdx.x;
    if (idx < R * C) {
        int r = idx % R, c = idx / R;      // out[idx] = in[r][c]
        u16 h, l;
        bsplit(in[(size_t)r * C + c], h, l);
        hi[idx] = h; lo[idx] = l;
    }
}

// ---------------- symmetric-normalized aggregation (CSR gather) ------------
// out[i] = (sum_{e: dst=i} h[src_e]*dinv[src_e] + h[i]*dinv[i]) * dinv[i] + b
// WF32: write fp32 output; WBF: write bf16 hi/lo planes.
template<int D, bool WF32, bool WBF>
__global__ __launch_bounds__(256) void k_agg(const float* __restrict__ h,
        const float* __restrict__ bias, float* __restrict__ outf,
        u16* __restrict__ outh, u16* __restrict__ outl, int n) {
    constexpr int TPN = D / 4;
    constexpr int NPB = 256 / TPN;
    int node = blockIdx.x * NPB + threadIdx.x / TPN;
    if (node >= n) return;
    int lane = threadIdx.x % TPN;

    const float4* hv = (const float4*)h;
    float di = g_dinv[node];

    float4 acc = hv[(size_t)node * TPN + lane];   // self loop
    acc.x *= di; acc.y *= di; acc.z *= di; acc.w *= di;

    int p = g_off[node], end = g_off[node + 1];
    for (; p + 1 < end; p += 2) {
        int s0 = g_srcs[p], s1 = g_srcs[p + 1];
        float w0 = g_w[p],  w1 = g_w[p + 1];
        float4 v0 = hv[(size_t)s0 * TPN + lane];
        float4 v1 = hv[(size_t)s1 * TPN + lane];
        acc.x += v0.x * w0 + v1.x * w1;
        acc.y += v0.y * w0 + v1.y * w1;
        acc.z += v0.z * w0 + v1.z * w1;
        acc.w += v0.w * w0 + v1.w * w1;
    }
    if (p < end) {
        int s = g_srcs[p]; float w = g_w[p];
        float4 v = hv[(size_t)s * TPN + lane];
        acc.x += v.x * w; acc.y += v.y * w; acc.z += v.z * w; acc.w += v.w * w;
    }

    float4 b = ((const float4*)bias)[lane];
    float4 o;
    o.x = acc.x * di + b.x;
    o.y = acc.y * di + b.y;
    o.z = acc.z * di + b.z;
    o.w = acc.w * di + b.w;
    if (WF32)
        ((float4*)outf)[(size_t)node * TPN + lane] = o;
    if (WBF) {
        ushort4 h4, l4;
        bsplit(o.x, h4.x, l4.x); bsplit(o.y, h4.y, l4.y);
        bsplit(o.z, h4.z, l4.z); bsplit(o.w, h4.w, l4.w);
        ((ushort4*)outh)[(size_t)node * TPN + lane] = h4;
        ((ushort4*)outl)[(size_t)node * TPN + lane] = l4;
    }
}

// ---------------- pipelined bf16x3 tensor-core GEMM ------------------------
// C[n,m] = sum_k A[n,k]*B[m,k] (+ bias[m]); A,B given as bf16 hi/lo planes.
// Block 128x128, BK=32, 3-stage cp.async pipeline, 8 warps (2x4), warp tile
// 64x32, mma.m16n8k16.bf16, products ah*bh + ah*bl + al*bh.

#define NSTG 3
#define BK2  32
#define SST  40                  // u16 per smem row (32 data + 8 pad, 80B)
#define TILE_SH (128 * SST)      // u16 per tile
#define SMEM_BYTES (NSTG * 4 * TILE_SH * 2)

__device__ __forceinline__ uint32_t su32(const void* p) {
    return (uint32_t)__cvta_generic_to_shared(p);
}

__device__ __forceinline__ void cpa16(uint32_t dst, const u16* src, int nbytes) {
    asm volatile("cp.async.cg.shared.global [%0], [%1], 16, %2;\n"
                 :: "r"(dst), "l"(src), "r"(nbytes));
}

__device__ __forceinline__ void mma_bf16(float* c, const uint32_t* a,
                                         const uint32_t* b) {
    asm volatile(
        "mma.sync.aligned.m16n8k16.row.col.f32.bf16.bf16.f32 "
        "{%0,%1,%2,%3}, {%4,%5,%6,%7}, {%8,%9}, {%0,%1,%2,%3};\n"
        : "+f"(c[0]), "+f"(c[1]), "+f"(c[2]), "+f"(c[3])
        : "r"(a[0]), "r"(a[1]), "r"(a[2]), "r"(a[3]), "r"(b[0]), "r"(b[1]));
}

__device__ __forceinline__ void load_stage(uint32_t sb,
        const u16* __restrict__ Ahp, const u16* __restrict__ Alp,
        const u16* __restrict__ Bhp, const u16* __restrict__ Blp,
        int rowBase, int colBase, int K, int nrows, int k0, int tid) {
    #pragma unroll
    for (int l = 0; l < 2; l++) {
        int q = tid * 2 + l;               // 0..511 16B chunks per tile
        int r = q >> 2;
        int kk = (q & 3) * 8;
        size_t aoff = (size_t)(rowBase + r) * K + k0 + kk;
        int pa = (rowBase + r < nrows) ? 16 : 0;
        cpa16(sb + (0 * TILE_SH + r * SST + kk) * 2, Ahp + aoff, pa);
        cpa16(sb + (1 * TILE_SH + r * SST + kk) * 2, Alp + aoff, pa);
        size_t boff = (size_t)(colBase + r) * K + k0 + kk;
        cpa16(sb + (2 * TILE_SH + r * SST + kk) * 2, Bhp + boff, 16);
        cpa16(sb + (3 * TILE_SH + r * SST + kk) * 2, Blp + boff, 16);
    }
}

__global__ __launch_bounds__(256, 1) void k_gemm(
        const u16* __restrict__ Ahp, const u16* __restrict__ Alp,
        const u16* __restrict__ Bhp, const u16* __restrict__ Blp,
        float* __restrict__ C, const float* __restrict__ bias,
        int nrows, int K, int M) {
    extern __shared__ __align__(16) u16 smem[];

    int tid = threadIdx.x;
    int rowBase = blockIdx.y * 128;
    int colBase = blockIdx.x * 128;
    uint32_t sbase = su32(smem);

    int lane = tid & 31, warp = tid >> 5;
    int wm = warp >> 2, wn = warp & 3;     // 2x4 warp grid, tile 64x32
    int gid = lane >> 2, tig = lane & 3;

    float acc[4][4][4];
    #pragma unroll
    for (int i = 0; i < 4; i++)
        #pragma unroll
        for (int j = 0; j < 4; j++)
            #pragma unroll
            for (int r = 0; r < 4; r++) acc[i][j][r] = 0.f;

    int niter = K / BK2;

    // prologue: stages 0,1
    #pragma unroll
    for (int s = 0; s < NSTG - 1; s++) {
        load_stage(sbase + s * 4 * TILE_SH * 2, Ahp, Alp, Bhp, Blp,
                   rowBase, colBase, K, nrows, s * BK2, tid);
        asm volatile("cp.async.commit_group;\n" ::: "memory");
    }

    for (int it = 0; it < niter; it++) {
        asm volatile("cp.async.wait_group 1;\n" ::: "memory");
        __syncthreads();

        int pre = it + NSTG - 1;
        if (pre < niter)
            load_stage(sbase + (pre % NSTG) * 4 * TILE_SH * 2, Ahp, Alp,
                       Bhp, Blp, rowBase, colBase, K, nrows, pre * BK2, tid);
        asm volatile("cp.async.commit_group;\n" ::: "memory");

        const u16* sAh = smem + (it % NSTG) * 4 * TILE_SH;
        const u16* sAl = sAh + TILE_SH;
        const u16* sBh = sAh + 2 * TILE_SH;
        const u16* sBl = sAh + 3 * TILE_SH;

        #pragma unroll
        for (int ks = 0; ks < BK2; ks += 16) {
            uint32_t ah[4][4], al[4][4], bh[4][2], bl[4][2];
            #pragma unroll
            for (int mt = 0; mt < 4; mt++) {
                int rm = wm * 64 + mt * 16 + gid;
                int o0 = rm * SST + ks + 2 * tig;
                int o1 = (rm + 8) * SST + ks + 2 * tig;
                ah[mt][0] = *(const uint32_t*)&sAh[o0];
                ah[mt][1] = *(const uint32_t*)&sAh[o1];
                ah[mt][2] = *(const uint32_t*)&sAh[o0 + 8];
                ah[mt][3] = *(const uint32_t*)&sAh[o1 + 8];
                al[mt][0] = *(const uint32_t*)&sAl[o0];
                al[mt][1] = *(const uint32_t*)&sAl[o1];
                al[mt][2] = *(const uint32_t*)&sAl[o0 + 8];
                al[mt][3] = *(const uint32_t*)&sAl[o1 + 8];
            }
            #pragma unroll
            for (int nt = 0; nt < 4; nt++) {
                int cn = wn * 32 + nt * 8 + gid;
                int o = cn * SST + ks + 2 * tig;
                bh[nt][0] = *(const uint32_t*)&sBh[o];
                bh[nt][1] = *(const uint32_t*)&sBh[o + 8];
                bl[nt][0] = *(const uint32_t*)&sBl[o];
                bl[nt][1] = *(const uint32_t*)&sBl[o + 8];
            }
            #pragma unroll
            for (int mt = 0; mt < 4; mt++)
                #pragma unroll
                for (int nt = 0; nt < 4; nt++) {
                    mma_bf16(acc[mt][nt], al[mt], bh[nt]);
                    mma_bf16(acc[mt][nt], ah[mt], bl[nt]);
                    mma_bf16(acc[mt][nt], ah[mt], bh[nt]);
                }
        }
    }

    // epilogue
    #pragma unroll
    for (int mt = 0; mt < 4; mt++) {
        int r0 = rowBase + wm * 64 + mt * 16 + gid;
        #pragma unroll
        for (int nt = 0; nt < 4; nt++) {
            int c = colBase + wn * 32 + nt * 8 + 2 * tig;
            float bx = 0.f, by = 0.f;
            if (bias) { bx = bias[c]; by = bias[c + 1]; }
            if (r0 < nrows)
                *(float2*)(C + (size_t)r0 * M + c) =
                    make_float2(acc[mt][nt][0] + bx, acc[mt][nt][1] + by);
            if (r0 + 8 < nrows)
                *(float2*)(C + (size_t)(r0 + 8) * M + c) =
                    make_float2(acc[mt][nt][2] + bx, acc[mt][nt][3] + by);
        }
    }
}

// ---------------- launch ----------------
extern "C" void kernel_launch(void* const* d_in, const int* in_sizes, int n_in,
                              void* d_out, int out_size) {
    const float* X  = (const float*)d_in[0];        // [N,1024]
    const void*  ei = d_in[1];                      // [2,E] int32 or int64
    const float* W1 = (const float*)d_in[2];        // [512,1024]
    const float* b1 = (const float*)d_in[3];        // [512]
    const float* W2 = (const float*)d_in[4];        // [128,512]
    const float* b2 = (const float*)d_in[5];        // [128]
    const float* b3 = (const float*)d_in[6];        // [512]
    const float* b4 = (const float*)d_in[7];        // [1024]
    const float* H1 = (const float*)d_in[8];        // [128,128]
    float* out = (float*)d_out;

    const int n = NN;
    const int e = in_sizes[1] / 2;

    // resolve device-global scratch addresses
    u16 *xh, *xl, *ah, *al;
    u16 *w1h, *w1l, *w1th, *w1tl, *w2h, *w2l, *w2th, *w2tl, *h1th, *h1tl;
    float *t, *zb;
    cudaGetSymbolAddress((void**)&xh, g_xh);
    cudaGetSymbolAddress((void**)&xl, g_xl);
    cudaGetSymbolAddress((void**)&ah, g_ah);
    cudaGetSymbolAddress((void**)&al, g_al);
    cudaGetSymbolAddress((void**)&t,  g_t);
    cudaGetSymbolAddress((void**)&zb, g_zbias);
    cudaGetSymbolAddress((void**)&w1h,  g_w1h);
    cudaGetSymbolAddress((void**)&w1l,  g_w1l);
    cudaGetSymbolAddress((void**)&w1th, g_w1th);
    cudaGetSymbolAddress((void**)&w1tl, g_w1tl);
    cudaGetSymbolAddress((void**)&w2h,  g_w2h);
    cudaGetSymbolAddress((void**)&w2l,  g_w2l);
    cudaGetSymbolAddress((void**)&w2th, g_w2th);
    cudaGetSymbolAddress((void**)&w2tl, g_w2tl);
    cudaGetSymbolAddress((void**)&h1th, g_h1th);
    cudaGetSymbolAddress((void**)&h1tl, g_h1tl);

    cudaFuncSetAttribute(k_gemm, cudaFuncAttributeMaxDynamicSharedMemorySize,
                         SMEM_BYTES);

    // output layout: (z, h2, h4) flattened in return order
    float* z  = out;
    float* h2 = out + (size_t)n * 128;
    float* h4 = out + (size_t)n * 256;

    int rtiles = (n + 127) / 128;
    int nb = (n + 255) / 256;

    // graph prep
    k_detect<<<1, 32>>>((const unsigned int*)ei);
    k_zero <<<(n + 255) / 256, 256>>>(n);
    k_count<<<(e + 255) / 256, 256>>>(ei, e);
    k_scan1<<<nb, 256>>>(n);
    k_scan2<<<1, 128>>>(nb);
    k_scan3<<<nb, 256>>>(n);
    k_fill <<<(e + 255) / 256, 256>>>(ei, e);

    // operand splits
    k_split<<<(n * 1024 / 4 + 255) / 256, 256>>>(X, xh, xl, n * 1024 / 4);
    k_split<<<(512 * 1024 / 4 + 255) / 256, 256>>>(W1, w1h, w1l, 512 * 1024 / 4);
    k_split<<<(128 * 512 / 4 + 255) / 256, 256>>>(W2, w2h, w2l, 128 * 512 / 4);
    k_split_t<<<(512 * 1024 + 255) / 256, 256>>>(W1, w1th, w1tl, 512, 1024);
    k_split_t<<<(128 * 512 + 255) / 256, 256>>>(W2, w2th, w2tl, 128, 512);
    k_split_t<<<(128 * 128 + 255) / 256, 256>>>(H1, h1th, h1tl, 128, 128);

    // conv1: t = X @ W1^T ; h1 -> bf16 planes
    k_gemm<<<dim3(4, rtiles), 256, SMEM_BYTES>>>(xh, xl, w1h, w1l, t, nullptr,
                                                 n, 1024, 512);
    k_agg<512, false, true><<<(n + 1) / 2, 256>>>(t, b1, nullptr, ah, al, n);

    // conv2: t = h1 @ W2^T ; h2 -> fp32 output AND bf16 planes
    k_gemm<<<dim3(1, rtiles), 256, SMEM_BYTES>>>(ah, al, w2h, w2l, t, nullptr,
                                                 n, 512, 128);
    k_agg<128, true, true><<<(n + 7) / 8, 256>>>(t, b2, h2, ah, al, n);

    // head: z = h2 @ head1
    k_gemm<<<dim3(1, rtiles), 256, SMEM_BYTES>>>(ah, al, h1th, h1tl, z, nullptr,
                                                 n, 128, 128);

    // conv3 (tied W2^T), commuted: h3 = (agg z) @ W2 + b3
    k_agg<128, false, true><<<(n + 7) / 8, 256>>>(z, zb, nullptr, ah, al, n);
    k_gemm<<<dim3(4, rtiles), 256, SMEM_BYTES>>>(ah, al, w2th, w2tl, t, b3,
                                                 n, 128, 512);

    // conv4 (tied W1^T), commuted: h4 = (agg h3) @ W1 + b4
    k_agg<512, false, true><<<(n + 1) / 2, 256>>>(t, zb, nullptr, ah, al, n);
    k_gemm<<<dim3(8, rtiles), 256, SMEM_BYTES>>>(ah, al, w1th, w1tl, h4, b4,
                                                 n, 512, 1024);
}